// round 1
// baseline (speedup 1.0000x reference)
#include <cuda_runtime.h>
#include <math.h>

#define BB   32
#define CC   2048
#define HWN  576
#define HW4  144       // HWN / 4 (float4 units)
#define PP   4
#define CHID 128       // C / RED
#define CP   8192      // C * P
#define NCHUNK 8
#define CHUNK  256     // CC / NCHUNK

// ---- scratch (no allocations allowed) ----
__device__ float g_pooled[BB * CC];             // (B, C)
__device__ float g_hidden[BB * CHID];           // (B, 128)
__device__ float g_dw[BB * CP];                 // (B, P*C) row = p*C + c
__device__ float g_beta[BB * PP];               // (B, P)
__device__ float g_part[NCHUNK * BB * PP * HWN]; // per-chunk partial logits

// ============================================================
// 1) pooled[b,c] = mean over HW.  One warp per (b,c) row.
// ============================================================
__global__ void k_pool(const float* __restrict__ x) {
    int warp = (blockIdx.x * blockDim.x + threadIdx.x) >> 5;   // 0..65535
    int lane = threadIdx.x & 31;
    const float4* xr = reinterpret_cast<const float4*>(x) + (size_t)warp * HW4;
    float s = 0.f;
    #pragma unroll
    for (int k = lane; k < HW4; k += 32) {
        float4 v = __ldg(&xr[k]);
        s += (v.x + v.y) + (v.z + v.w);
    }
    #pragma unroll
    for (int o = 16; o; o >>= 1) s += __shfl_xor_sync(0xffffffffu, s, o);
    if (lane == 0) g_pooled[warp] = s * (1.0f / 576.0f);
}

// ============================================================
// 2) hidden[b,j] = silu(dot(pooled[b,:], fc1_w[j,:]) + fc1_b[j])
//    One warp per (b,j) output. 4096 warps.
// ============================================================
__global__ void k_fc1(const float* __restrict__ fc1_w,
                      const float* __restrict__ fc1_b) {
    int warp = (blockIdx.x * blockDim.x + threadIdx.x) >> 5;   // 0..4095
    int lane = threadIdx.x & 31;
    int b = warp >> 7;
    int j = warp & 127;
    const float4* pr = reinterpret_cast<const float4*>(g_pooled) + (size_t)b * (CC / 4);
    const float4* wr = reinterpret_cast<const float4*>(fc1_w)    + (size_t)j * (CC / 4);
    float s = 0.f;
    #pragma unroll 4
    for (int k = lane; k < CC / 4; k += 32) {
        float4 a = pr[k];
        float4 w = __ldg(&wr[k]);
        s += a.x * w.x + a.y * w.y + a.z * w.z + a.w * w.w;
    }
    #pragma unroll
    for (int o = 16; o; o >>= 1) s += __shfl_xor_sync(0xffffffffu, s, o);
    if (lane == 0) {
        float z = s + fc1_b[j];
        g_hidden[b * CHID + j] = z / (1.0f + expf(-z));
    }
}

// ============================================================
// 3) dw[b, row] = dot(hidden[b,:], fc2_w[row,:]) + fc2_b[row]
//    Block handles 256 rows x 8 batches. Grid = 32 rowchunks * 4 bgroups.
// ============================================================
__global__ void k_fc2(const float* __restrict__ fc2_w,
                      const float* __restrict__ fc2_b) {
    __shared__ float4 hs[8 * 32];  // 8 batches * 128 floats (as float4)
    int rc = blockIdx.x & 31;      // row chunk
    int bg = blockIdx.x >> 5;      // batch group (0..3)
    int t  = threadIdx.x;          // 0..255

    hs[t] = reinterpret_cast<const float4*>(g_hidden)[bg * 256 + t];
    __syncthreads();

    int row = rc * 256 + t;
    const float4* wr = reinterpret_cast<const float4*>(fc2_w) + (size_t)row * 32;
    float acc[8];
    #pragma unroll
    for (int bb = 0; bb < 8; bb++) acc[bb] = 0.f;

    #pragma unroll 4
    for (int j4 = 0; j4 < 32; j4++) {
        float4 w = __ldg(&wr[j4]);
        #pragma unroll
        for (int bb = 0; bb < 8; bb++) {
            float4 h = hs[bb * 32 + j4];   // broadcast read
            acc[bb] += w.x * h.x + w.y * h.y + w.z * h.z + w.w * h.w;
        }
    }
    float bias = fc2_b[row];
    #pragma unroll
    for (int bb = 0; bb < 8; bb++)
        g_dw[(size_t)(bg * 8 + bb) * CP + row] = acc[bb] + bias;
}

// ============================================================
// 4) beta[b,p] = sum_c conv_b[c] * dw[b,p,c].  Warp per (b,p).
// ============================================================
__global__ void k_beta(const float* __restrict__ conv_b) {
    int warp = (blockIdx.x * blockDim.x + threadIdx.x) >> 5;   // 0..127
    int lane = threadIdx.x & 31;
    int b = warp >> 2;
    int p = warp & 3;
    const float4* dr = reinterpret_cast<const float4*>(g_dw) + ((size_t)b * CP + p * CC) / 4;
    const float4* cb = reinterpret_cast<const float4*>(conv_b);
    float s = 0.f;
    #pragma unroll 4
    for (int k = lane; k < CC / 4; k += 32) {
        float4 d = dr[k];
        float4 c = __ldg(&cb[k]);
        s += d.x * c.x + d.y * c.y + d.z * c.z + d.w * c.w;
    }
    #pragma unroll
    for (int o = 16; o; o >>= 1) s += __shfl_xor_sync(0xffffffffu, s, o);
    if (lane == 0) g_beta[b * PP + p] = s;
}

// ============================================================
// 5) Main pass: partial[ch,b,p,hw] = sum_{c in chunk} x[b,c,hw] * wcomb[p,c]
//    wcomb[p,c] = conv_w[c] * dw[b,p,c].
//    Grid: (b * NCHUNK) blocks of 576 threads.
//    Thread t: hw-quad q = t%144, channel sub-lane cl = t/4... (t/144).
// ============================================================
__global__ void __launch_bounds__(576) k_einsum(const float* __restrict__ x,
                                                const float* __restrict__ conv_w) {
    __shared__ float  wcomb[PP][CHUNK];          // 4 KB
    __shared__ float4 red[PP][4][HW4];           // 36 KB

    int b  = blockIdx.x >> 3;
    int ch = blockIdx.x & 7;
    int c0 = ch * CHUNK;
    int t  = threadIdx.x;                        // 0..575

    for (int idx = t; idx < PP * CHUNK; idx += 576) {
        int p = idx >> 8;        // /256
        int c = idx & 255;
        wcomb[p][c] = __ldg(&conv_w[c0 + c]) * g_dw[(size_t)b * CP + p * CC + c0 + c];
    }
    __syncthreads();

    int q  = t % HW4;
    int cl = t / HW4;            // 0..3
    const float4* xr = reinterpret_cast<const float4*>(x)
                     + ((size_t)b * CC + c0 + cl) * HW4 + q;

    float4 a0 = {0,0,0,0}, a1 = a0, a2 = a0, a3 = a0;
    #pragma unroll 8
    for (int i = 0; i < CHUNK / 4; i++) {
        int c = cl + i * 4;
        float4 v = __ldg(xr);
        xr += 4 * HW4;
        float w0 = wcomb[0][c], w1 = wcomb[1][c], w2 = wcomb[2][c], w3 = wcomb[3][c];
        a0.x += v.x * w0; a0.y += v.y * w0; a0.z += v.z * w0; a0.w += v.w * w0;
        a1.x += v.x * w1; a1.y += v.y * w1; a1.z += v.z * w1; a1.w += v.w * w1;
        a2.x += v.x * w2; a2.y += v.y * w2; a2.z += v.z * w2; a2.w += v.w * w2;
        a3.x += v.x * w3; a3.y += v.y * w3; a3.z += v.z * w3; a3.w += v.w * w3;
    }
    red[0][cl][q] = a0;
    red[1][cl][q] = a1;
    red[2][cl][q] = a2;
    red[3][cl][q] = a3;
    __syncthreads();

    // 576 threads == PP * HW4 outputs: sum across the 4 channel sub-lanes
    int p  = t / HW4;
    int qq = t % HW4;
    float4 r0 = red[p][0][qq], r1 = red[p][1][qq], r2 = red[p][2][qq], r3 = red[p][3][qq];
    float4 s;
    s.x = (r0.x + r1.x) + (r2.x + r3.x);
    s.y = (r0.y + r1.y) + (r2.y + r3.y);
    s.z = (r0.z + r1.z) + (r2.z + r3.z);
    s.w = (r0.w + r1.w) + (r2.w + r3.w);
    reinterpret_cast<float4*>(g_part)[(((size_t)ch * BB + b) * PP + p) * HW4 + qq] = s;
}

// ============================================================
// 6) Sum partials + beta, softmax over P, write output (B,P,H,W).
// ============================================================
__global__ void k_softmax(float* __restrict__ out) {
    int tg = blockIdx.x * blockDim.x + threadIdx.x;
    if (tg >= BB * HW4) return;
    int b = tg / HW4;
    int q = tg % HW4;

    float4 s[PP];
    #pragma unroll
    for (int p = 0; p < PP; p++) {
        float beta = g_beta[b * PP + p];
        float4 acc = {beta, beta, beta, beta};
        #pragma unroll
        for (int ch = 0; ch < NCHUNK; ch++) {
            float4 v = reinterpret_cast<const float4*>(g_part)
                           [(((size_t)ch * BB + b) * PP + p) * HW4 + q];
            acc.x += v.x; acc.y += v.y; acc.z += v.z; acc.w += v.w;
        }
        s[p] = acc;
    }

    float4 m = s[0];
    #pragma unroll
    for (int p = 1; p < PP; p++) {
        m.x = fmaxf(m.x, s[p].x); m.y = fmaxf(m.y, s[p].y);
        m.z = fmaxf(m.z, s[p].z); m.w = fmaxf(m.w, s[p].w);
    }
    float4 e[PP];
    float4 sum = {0,0,0,0};
    #pragma unroll
    for (int p = 0; p < PP; p++) {
        e[p].x = expf(s[p].x - m.x); e[p].y = expf(s[p].y - m.y);
        e[p].z = expf(s[p].z - m.z); e[p].w = expf(s[p].w - m.w);
        sum.x += e[p].x; sum.y += e[p].y; sum.z += e[p].z; sum.w += e[p].w;
    }
    float4 inv;
    inv.x = 1.f / sum.x; inv.y = 1.f / sum.y; inv.z = 1.f / sum.z; inv.w = 1.f / sum.w;
    #pragma unroll
    for (int p = 0; p < PP; p++) {
        float4 o;
        o.x = e[p].x * inv.x; o.y = e[p].y * inv.y;
        o.z = e[p].z * inv.z; o.w = e[p].w * inv.w;
        reinterpret_cast<float4*>(out)[((size_t)b * PP + p) * HW4 + q] = o;
    }
}

extern "C" void kernel_launch(void* const* d_in, const int* in_sizes, int n_in,
                              void* d_out, int out_size) {
    const float* x      = (const float*)d_in[0];
    const float* fc1_w  = (const float*)d_in[1];
    const float* fc1_b  = (const float*)d_in[2];
    const float* fc2_w  = (const float*)d_in[3];
    const float* fc2_b  = (const float*)d_in[4];
    const float* conv_w = (const float*)d_in[5];
    const float* conv_b = (const float*)d_in[6];
    float* out = (float*)d_out;

    k_pool   <<<(BB * CC) / 8, 256>>>(x);          // 8192 blocks, warp/row
    k_fc1    <<<(BB * CHID) / 8, 256>>>(fc1_w, fc1_b);   // 512 blocks
    k_fc2    <<<128, 256>>>(fc2_w, fc2_b);
    k_beta   <<<16, 256>>>(conv_b);
    k_einsum <<<BB * NCHUNK, 576>>>(x, conv_w);    // 256 blocks
    k_softmax<<<(BB * HW4 + 255) / 256, 256>>>(out);
}